// round 1
// baseline (speedup 1.0000x reference)
#include <cuda_runtime.h>

// Batched weighted Kabsch via Horn's quaternion method.
// One thread = one batch. Single streaming pass builds the weighted
// cross-covariance; 4x4 Jacobi eigensolver (fully unrolled, register-resident)
// extracts the optimal rotation quaternion.

#define NSWEEPS 6

__global__ __launch_bounds__(128)
void kabsch_kernel(const float* __restrict__ A,
                   const float* __restrict__ B,
                   const float* __restrict__ W,
                   float* __restrict__ out, int bs)
{
    int b = blockIdx.x * blockDim.x + threadIdx.x;
    if (b >= bs) return;

    const float4* a4 = reinterpret_cast<const float4*>(A) + (long)b * 15;
    const float4* b4 = reinterpret_cast<const float4*>(B) + (long)b * 15;
    const float4* w4 = reinterpret_cast<const float4*>(W) + (long)b * 5;

    float Sw = 0.f;
    float Sa0 = 0.f, Sa1 = 0.f, Sa2 = 0.f;
    float Sb0 = 0.f, Sb1 = 0.f, Sb2 = 0.f;
    float S00 = 0.f, S01 = 0.f, S02 = 0.f;
    float S10 = 0.f, S11 = 0.f, S12 = 0.f;
    float S20 = 0.f, S21 = 0.f, S22 = 0.f;

    #pragma unroll
    for (int c = 0; c < 5; c++) {
        float4 wv = w4[c];
        float4 A0 = a4[3*c + 0], A1 = a4[3*c + 1], A2 = a4[3*c + 2];
        float4 B0 = b4[3*c + 0], B1 = b4[3*c + 1], B2 = b4[3*c + 2];
        float af[12] = {A0.x, A0.y, A0.z, A0.w, A1.x, A1.y, A1.z, A1.w,
                        A2.x, A2.y, A2.z, A2.w};
        float bf[12] = {B0.x, B0.y, B0.z, B0.w, B1.x, B1.y, B1.z, B1.w,
                        B2.x, B2.y, B2.z, B2.w};
        float wf[4]  = {wv.x, wv.y, wv.z, wv.w};
        #pragma unroll
        for (int p = 0; p < 4; p++) {
            float w = (wf[p] < 0.0f) ? 0.0f : wf[p];
            float ax = af[3*p + 0], ay = af[3*p + 1], az = af[3*p + 2];
            float bx = bf[3*p + 0], by = bf[3*p + 1], bz = bf[3*p + 2];
            Sw += w;
            float wax = w * ax, way = w * ay, waz = w * az;
            Sa0 += wax; Sa1 += way; Sa2 += waz;
            Sb0 += w * bx; Sb1 += w * by; Sb2 += w * bz;
            S00 += wax * bx; S01 += wax * by; S02 += wax * bz;
            S10 += way * bx; S11 += way * by; S12 += way * bz;
            S20 += waz * bx; S21 += waz * by; S22 += waz * bz;
        }
    }

    // Centering fixup: H = Sab - Sa*Sb^T * (W'+eps)/W'^2, W' = Sw + eps.
    // Algebraically identical to reference's subtract-centroid form.
    const float EPS = 1e-6f;
    float Wp  = Sw + EPS;
    float inv = 1.0f / Wp;
    float factor = (Wp + EPS) * inv * inv;
    S00 -= factor * Sa0 * Sb0; S01 -= factor * Sa0 * Sb1; S02 -= factor * Sa0 * Sb2;
    S10 -= factor * Sa1 * Sb0; S11 -= factor * Sa1 * Sb1; S12 -= factor * Sa1 * Sb2;
    S20 -= factor * Sa2 * Sb0; S21 -= factor * Sa2 * Sb1; S22 -= factor * Sa2 * Sb2;

    float cA0 = Sa0 * inv, cA1 = Sa1 * inv, cA2 = Sa2 * inv;
    float cB0 = Sb0 * inv, cB1 = Sb1 * inv, cB2 = Sb2 * inv;

    // Horn's 4x4 symmetric matrix (S_ij = sum w * Am_i * Bm_j).
    float n[4][4];
    n[0][0] = S00 + S11 + S22;
    n[0][1] = S12 - S21;
    n[0][2] = S20 - S02;
    n[0][3] = S01 - S10;
    n[1][1] = S00 - S11 - S22;
    n[1][2] = S01 + S10;
    n[1][3] = S20 + S02;
    n[2][2] = S11 - S00 - S22;
    n[2][3] = S12 + S21;
    n[3][3] = S22 - S00 - S11;
    n[1][0] = n[0][1]; n[2][0] = n[0][2]; n[3][0] = n[0][3];
    n[2][1] = n[1][2]; n[3][1] = n[1][3]; n[3][2] = n[2][3];

    float v[4][4] = {{1.f,0.f,0.f,0.f},{0.f,1.f,0.f,0.f},
                     {0.f,0.f,1.f,0.f},{0.f,0.f,0.f,1.f}};

    // Cyclic Jacobi, fully unrolled -> all array indices compile-time constant.
    #pragma unroll
    for (int sweep = 0; sweep < NSWEEPS; sweep++) {
        #pragma unroll
        for (int pair = 0; pair < 6; pair++) {
            const int PP[6] = {0, 0, 0, 1, 1, 2};
            const int QQ[6] = {1, 2, 3, 2, 3, 3};
            const int p = PP[pair];
            const int q = QQ[pair];
            float apq = n[p][q];
            float app = n[p][p];
            float aqq = n[q][q];
            float t;
            if (apq != 0.0f) {
                float theta = 0.5f * (aqq - app) / apq;
                t = copysignf(1.0f, theta) /
                    (fabsf(theta) + sqrtf(theta * theta + 1.0f));
            } else {
                t = 0.0f;
            }
            float cc = rsqrtf(t * t + 1.0f);
            float ss = t * cc;

            n[p][p] = app - t * apq;
            n[q][q] = aqq + t * apq;
            n[p][q] = 0.0f; n[q][p] = 0.0f;
            #pragma unroll
            for (int k = 0; k < 4; k++) {
                if (k != p && k != q) {
                    float akp = n[k][p], akq = n[k][q];
                    float np = cc * akp - ss * akq;
                    float nq = ss * akp + cc * akq;
                    n[k][p] = np; n[p][k] = np;
                    n[k][q] = nq; n[q][k] = nq;
                }
            }
            #pragma unroll
            for (int k = 0; k < 4; k++) {
                float vkp = v[k][p], vkq = v[k][q];
                v[k][p] = cc * vkp - ss * vkq;
                v[k][q] = ss * vkp + cc * vkq;
            }
        }
    }

    // Select eigenvector of largest eigenvalue (branchless selects, static idx).
    float bv = n[0][0];
    float q0 = v[0][0], qx = v[1][0], qy = v[2][0], qz = v[3][0];
    #pragma unroll
    for (int k = 1; k < 4; k++) {
        bool gt = n[k][k] > bv;
        bv = gt ? n[k][k] : bv;
        q0 = gt ? v[0][k] : q0;
        qx = gt ? v[1][k] : qx;
        qy = gt ? v[2][k] : qy;
        qz = gt ? v[3][k] : qz;
    }
    float qn = rsqrtf(q0*q0 + qx*qx + qy*qy + qz*qz);
    q0 *= qn; qx *= qn; qy *= qn; qz *= qn;

    // Quaternion -> rotation (b ~= R a).
    float xx = qx*qx, yy = qy*qy, zz = qz*qz;
    float xy = qx*qy, xz = qx*qz, yz = qy*qz;
    float wx = q0*qx, wy = q0*qy, wz = q0*qz;
    float r00 = 1.0f - 2.0f*(yy + zz);
    float r01 = 2.0f*(xy - wz);
    float r02 = 2.0f*(xz + wy);
    float r10 = 2.0f*(xy + wz);
    float r11 = 1.0f - 2.0f*(xx + zz);
    float r12 = 2.0f*(yz - wx);
    float r20 = 2.0f*(xz - wy);
    float r21 = 2.0f*(yz + wx);
    float r22 = 1.0f - 2.0f*(xx + yy);

    float t0 = cB0 - (r00*cA0 + r01*cA1 + r02*cA2);
    float t1 = cB1 - (r10*cA0 + r11*cA1 + r12*cA2);
    float t2 = cB2 - (r20*cA0 + r21*cA1 + r22*cA2);

    float4* o = reinterpret_cast<float4*>(out) + (long)b * 4;
    o[0] = make_float4(r00, r01, r02, t0);
    o[1] = make_float4(r10, r11, r12, t1);
    o[2] = make_float4(r20, r21, r22, t2);
    o[3] = make_float4(0.0f, 0.0f, 0.0f, 1.0f);
}

extern "C" void kernel_launch(void* const* d_in, const int* in_sizes, int n_in,
                              void* d_out, int out_size)
{
    const float* A = (const float*)d_in[0];
    const float* B = (const float*)d_in[1];
    const float* W = (const float*)d_in[2];
    int bs = in_sizes[2] / 20;   // weights: [bs, 20]
    int threads = 128;
    int blocks = (bs + threads - 1) / threads;
    kabsch_kernel<<<blocks, threads>>>(A, B, W, (float*)d_out, bs);
}

// round 2
// speedup vs baseline: 1.7719x; 1.7719x over previous
#include <cuda_runtime.h>

// Batched weighted Kabsch via Horn's quaternion method, closed-form eigen.
// One thread = one batch. Single streaming pass builds the weighted
// cross-covariance H; largest eigenvalue of Horn's 4x4 N via Newton on the
// quartic (coefficients from invariants of H), eigenvector via adjugate.

__global__ __launch_bounds__(128)
void kabsch_kernel(const float* __restrict__ A,
                   const float* __restrict__ B,
                   const float* __restrict__ W,
                   float* __restrict__ out, int bs)
{
    int b = blockIdx.x * blockDim.x + threadIdx.x;
    if (b >= bs) return;

    const float4* a4 = reinterpret_cast<const float4*>(A) + (long)b * 15;
    const float4* b4 = reinterpret_cast<const float4*>(B) + (long)b * 15;
    const float4* w4 = reinterpret_cast<const float4*>(W) + (long)b * 5;

    float Sw = 0.f;
    float Sa0 = 0.f, Sa1 = 0.f, Sa2 = 0.f;
    float Sb0 = 0.f, Sb1 = 0.f, Sb2 = 0.f;
    float S00 = 0.f, S01 = 0.f, S02 = 0.f;
    float S10 = 0.f, S11 = 0.f, S12 = 0.f;
    float S20 = 0.f, S21 = 0.f, S22 = 0.f;

    #pragma unroll
    for (int c = 0; c < 5; c++) {
        float4 wv = w4[c];
        float4 A0 = a4[3*c + 0], A1 = a4[3*c + 1], A2 = a4[3*c + 2];
        float4 B0 = b4[3*c + 0], B1 = b4[3*c + 1], B2 = b4[3*c + 2];
        float af[12] = {A0.x, A0.y, A0.z, A0.w, A1.x, A1.y, A1.z, A1.w,
                        A2.x, A2.y, A2.z, A2.w};
        float bf[12] = {B0.x, B0.y, B0.z, B0.w, B1.x, B1.y, B1.z, B1.w,
                        B2.x, B2.y, B2.z, B2.w};
        float wf[4]  = {wv.x, wv.y, wv.z, wv.w};
        #pragma unroll
        for (int p = 0; p < 4; p++) {
            float w = (wf[p] < 0.0f) ? 0.0f : wf[p];
            float ax = af[3*p + 0], ay = af[3*p + 1], az = af[3*p + 2];
            float bx = bf[3*p + 0], by = bf[3*p + 1], bz = bf[3*p + 2];
            Sw += w;
            float wax = w * ax, way = w * ay, waz = w * az;
            Sa0 += wax; Sa1 += way; Sa2 += waz;
            Sb0 += w * bx; Sb1 += w * by; Sb2 += w * bz;
            S00 += wax * bx; S01 += wax * by; S02 += wax * bz;
            S10 += way * bx; S11 += way * by; S12 += way * bz;
            S20 += waz * bx; S21 += waz * by; S22 += waz * bz;
        }
    }

    // Centering fixup: H = Sab - Sa*Sb^T * (W'+eps)/W'^2, W' = Sw + eps.
    const float EPS = 1e-6f;
    float Wp  = Sw + EPS;
    float inv = 1.0f / Wp;
    float factor = (Wp + EPS) * inv * inv;
    S00 -= factor * Sa0 * Sb0; S01 -= factor * Sa0 * Sb1; S02 -= factor * Sa0 * Sb2;
    S10 -= factor * Sa1 * Sb0; S11 -= factor * Sa1 * Sb1; S12 -= factor * Sa1 * Sb2;
    S20 -= factor * Sa2 * Sb0; S21 -= factor * Sa2 * Sb1; S22 -= factor * Sa2 * Sb2;

    float cA0 = Sa0 * inv, cA1 = Sa1 * inv, cA2 = Sa2 * inv;
    float cB0 = Sb0 * inv, cB1 = Sb1 * inv, cB2 = Sb2 * inv;

    // Normalize H by Frobenius norm (scale-invariant rotation).
    float f2 = S00*S00 + S01*S01 + S02*S02
             + S10*S10 + S11*S11 + S12*S12
             + S20*S20 + S21*S21 + S22*S22;
    float sc = rsqrtf(f2 + 1e-30f);
    float h00 = S00*sc, h01 = S01*sc, h02 = S02*sc;
    float h10 = S10*sc, h11 = S11*sc, h12 = S12*sc;
    float h20 = S20*sc, h21 = S21*sc, h22 = S22*sc;

    // Cofactor matrix of H (general 3x3), det(H), ||cof||^2.
    float c00 =  (h11*h22 - h12*h21);
    float c01 = -(h10*h22 - h12*h20);
    float c02 =  (h10*h21 - h11*h20);
    float c10 = -(h01*h22 - h02*h21);
    float c11 =  (h00*h22 - h02*h20);
    float c12 = -(h00*h21 - h01*h20);
    float c20 =  (h01*h12 - h02*h11);
    float c21 = -(h00*h12 - h02*h10);
    float c22 =  (h00*h11 - h01*h10);
    float detH = h00*c00 + h01*c01 + h02*c02;
    float cof2 = c00*c00 + c01*c01 + c02*c02
               + c10*c10 + c11*c11 + c12*c12
               + c20*c20 + c21*c21 + c22*c22;
    float fn = (f2 + 1e-30f) * sc * sc;   // ~1.0 exactly-scaled Frobenius^2

    // Char poly of Horn's N: l^4 + C2 l^2 + C1 l + C0.
    float C2 = -2.0f * fn;
    float C1 = -8.0f * detH;
    float C0 = fn * fn - 4.0f * cof2;

    // Newton from above (lmax <= sqrt(3) after normalization).
    float lam = 1.7320508f;
    #pragma unroll
    for (int it = 0; it < 12; it++) {
        float l2 = lam * lam;
        float fv = ((l2 + C2) * lam + C1) * lam + C0;
        float fp = (4.0f * l2 + 2.0f * C2) * lam + C1;
        lam -= __fdividef(fv, fp);
    }

    // M = N - lam*I (Horn's 4x4, symmetric).
    float m00 = (h00 + h11 + h22) - lam;
    float m01 = h12 - h21;
    float m02 = h20 - h02;
    float m03 = h01 - h10;
    float m11 = (h00 - h11 - h22) - lam;
    float m12 = h01 + h10;
    float m13 = h20 + h02;
    float m22 = (h11 - h00 - h22) - lam;
    float m23 = h12 + h21;
    float m33 = (h22 - h00 - h11) - lam;

    // Symmetric adjugate of M = c * v v^T; 10 unique entries.
    #define DET3(a,b,c,d,e,f,g,h,i) ((a)*((e)*(i)-(f)*(h)) - (b)*((d)*(i)-(f)*(g)) + (c)*((d)*(h)-(e)*(g)))
    float A00 =  DET3(m11,m12,m13, m12,m22,m23, m13,m23,m33);
    float A11 =  DET3(m00,m02,m03, m02,m22,m23, m03,m23,m33);
    float A22 =  DET3(m00,m01,m03, m01,m11,m13, m03,m13,m33);
    float A33 =  DET3(m00,m01,m02, m01,m11,m12, m02,m12,m22);
    float A01 = -DET3(m01,m12,m13, m02,m22,m23, m03,m23,m33);
    float A02 =  DET3(m01,m11,m13, m02,m12,m23, m03,m13,m33);
    float A03 = -DET3(m01,m11,m12, m02,m12,m22, m03,m13,m23);
    float A12 = -DET3(m00,m01,m03, m02,m12,m23, m03,m13,m33);
    float A13 =  DET3(m00,m01,m02, m02,m12,m22, m03,m13,m23);
    float A23 = -DET3(m00,m01,m02, m01,m11,m12, m03,m13,m23);
    #undef DET3

    // Pick the column with the largest |diagonal| (adj = c*vv^T, diag = c*v_k^2).
    float best = fabsf(A00);
    float q0 = A00, qx = A01, qy = A02, qz = A03;
    float d1 = fabsf(A11);
    if (d1 > best) { best = d1; q0 = A01; qx = A11; qy = A12; qz = A13; }
    float d2 = fabsf(A22);
    if (d2 > best) { best = d2; q0 = A02; qx = A12; qy = A22; qz = A23; }
    float d3 = fabsf(A33);
    if (d3 > best) { best = d3; q0 = A03; qx = A13; qy = A23; qz = A33; }

    float qn = rsqrtf(q0*q0 + qx*qx + qy*qy + qz*qz + 1e-30f);
    q0 *= qn; qx *= qn; qy *= qn; qz *= qn;

    // Quaternion -> rotation.
    float xx = qx*qx, yy = qy*qy, zz = qz*qz;
    float xy = qx*qy, xz = qx*qz, yz = qy*qz;
    float wx = q0*qx, wy = q0*qy, wz = q0*qz;
    float r00 = 1.0f - 2.0f*(yy + zz);
    float r01 = 2.0f*(xy - wz);
    float r02 = 2.0f*(xz + wy);
    float r10 = 2.0f*(xy + wz);
    float r11 = 1.0f - 2.0f*(xx + zz);
    float r12 = 2.0f*(yz - wx);
    float r20 = 2.0f*(xz - wy);
    float r21 = 2.0f*(yz + wx);
    float r22 = 1.0f - 2.0f*(xx + yy);

    float t0 = cB0 - (r00*cA0 + r01*cA1 + r02*cA2);
    float t1 = cB1 - (r10*cA0 + r11*cA1 + r12*cA2);
    float t2 = cB2 - (r20*cA0 + r21*cA1 + r22*cA2);

    float4* o = reinterpret_cast<float4*>(out) + (long)b * 4;
    o[0] = make_float4(r00, r01, r02, t0);
    o[1] = make_float4(r10, r11, r12, t1);
    o[2] = make_float4(r20, r21, r22, t2);
    o[3] = make_float4(0.0f, 0.0f, 0.0f, 1.0f);
}

extern "C" void kernel_launch(void* const* d_in, const int* in_sizes, int n_in,
                              void* d_out, int out_size)
{
    const float* A = (const float*)d_in[0];
    const float* B = (const float*)d_in[1];
    const float* W = (const float*)d_in[2];
    int bs = in_sizes[2] / 20;   // weights: [bs, 20]
    int threads = 128;
    int blocks = (bs + threads - 1) / threads;
    kabsch_kernel<<<blocks, threads>>>(A, B, W, (float*)d_out, bs);
}

// round 3
// speedup vs baseline: 2.0639x; 1.1648x over previous
#include <cuda_runtime.h>
#include <cstdint>

// Batched weighted Kabsch, Horn quaternion + closed-form quartic eigen.
// Warp-cooperative cp.async staging: each warp stages its 32 consecutive
// batches' A/B/W slices (contiguous in gmem, fully coalesced) into smem,
// then each lane solves one batch from smem (conflict-free LDS.128).

#define BPW 32                    // batches per warp
#define WARPS 2                   // warps per CTA
#define BPC (BPW * WARPS)         // batches per CTA

__device__ __forceinline__ void cp16(uint32_t dst, const void* src, bool pred) {
    asm volatile(
        "{\n\t.reg .pred p;\n\t"
        "setp.ne.u32 p, %2, 0;\n\t"
        "@p cp.async.cg.shared.global [%0], [%1], 16;\n\t}"
        :: "r"(dst), "l"(src), "r"((int)pred));
}

__global__ __launch_bounds__(WARPS * 32)
void kabsch_kernel(const float4* __restrict__ A4,
                   const float4* __restrict__ B4,
                   const float4* __restrict__ W4,
                   float* __restrict__ out, int bs)
{
    __shared__ float4 sA[WARPS][BPW * 15];
    __shared__ float4 sB[WARPS][BPW * 15];
    __shared__ float4 sW[WARPS][BPW * 5];

    const int warp = threadIdx.x >> 5;
    const int lane = threadIdx.x & 31;
    const long wb0 = (long)blockIdx.x * BPC + warp * BPW;

    const long aBase = wb0 * 15;              // in float4 units
    const long wBase = wb0 * 5;
    const long aLim  = (long)bs * 15;
    const long wLim  = (long)bs * 5;

    uint32_t sa = (uint32_t)__cvta_generic_to_shared(&sA[warp][0]);
    uint32_t sb = (uint32_t)__cvta_generic_to_shared(&sB[warp][0]);
    uint32_t sw = (uint32_t)__cvta_generic_to_shared(&sW[warp][0]);

    #pragma unroll
    for (int i = 0; i < 15; i++) {
        int  o   = i * 32 + lane;
        long idx = aBase + o;
        bool ok  = idx < aLim;
        cp16(sa + o * 16, A4 + idx, ok);
        cp16(sb + o * 16, B4 + idx, ok);
    }
    #pragma unroll
    for (int i = 0; i < 5; i++) {
        int  o   = i * 32 + lane;
        long idx = wBase + o;
        cp16(sw + o * 16, W4 + idx, idx < wLim);
    }
    asm volatile("cp.async.commit_group;" ::: "memory");
    asm volatile("cp.async.wait_group 0;" ::: "memory");
    __syncwarp();

    const long b = wb0 + lane;
    if (b >= bs) return;

    const float4* a4 = &sA[warp][lane * 15];
    const float4* b4 = &sB[warp][lane * 15];
    const float4* w4 = &sW[warp][lane * 5];

    float Sw = 0.f;
    float Sa0 = 0.f, Sa1 = 0.f, Sa2 = 0.f;
    float Sb0 = 0.f, Sb1 = 0.f, Sb2 = 0.f;
    float S00 = 0.f, S01 = 0.f, S02 = 0.f;
    float S10 = 0.f, S11 = 0.f, S12 = 0.f;
    float S20 = 0.f, S21 = 0.f, S22 = 0.f;

    #pragma unroll
    for (int c = 0; c < 5; c++) {
        float4 wv = w4[c];
        float4 A0 = a4[3*c + 0], A1 = a4[3*c + 1], A2 = a4[3*c + 2];
        float4 B0 = b4[3*c + 0], B1 = b4[3*c + 1], B2 = b4[3*c + 2];
        float af[12] = {A0.x, A0.y, A0.z, A0.w, A1.x, A1.y, A1.z, A1.w,
                        A2.x, A2.y, A2.z, A2.w};
        float bf[12] = {B0.x, B0.y, B0.z, B0.w, B1.x, B1.y, B1.z, B1.w,
                        B2.x, B2.y, B2.z, B2.w};
        float wf[4]  = {wv.x, wv.y, wv.z, wv.w};
        #pragma unroll
        for (int p = 0; p < 4; p++) {
            float w = (wf[p] < 0.0f) ? 0.0f : wf[p];
            float ax = af[3*p + 0], ay = af[3*p + 1], az = af[3*p + 2];
            float bx = bf[3*p + 0], by = bf[3*p + 1], bz = bf[3*p + 2];
            Sw += w;
            float wax = w * ax, way = w * ay, waz = w * az;
            Sa0 += wax; Sa1 += way; Sa2 += waz;
            Sb0 += w * bx; Sb1 += w * by; Sb2 += w * bz;
            S00 += wax * bx; S01 += wax * by; S02 += wax * bz;
            S10 += way * bx; S11 += way * by; S12 += way * bz;
            S20 += waz * bx; S21 += waz * by; S22 += waz * bz;
        }
    }

    // Centering fixup: H = Sab - Sa*Sb^T * (W'+eps)/W'^2, W' = Sw + eps.
    const float EPS = 1e-6f;
    float Wp  = Sw + EPS;
    float inv = 1.0f / Wp;
    float factor = (Wp + EPS) * inv * inv;
    S00 -= factor * Sa0 * Sb0; S01 -= factor * Sa0 * Sb1; S02 -= factor * Sa0 * Sb2;
    S10 -= factor * Sa1 * Sb0; S11 -= factor * Sa1 * Sb1; S12 -= factor * Sa1 * Sb2;
    S20 -= factor * Sa2 * Sb0; S21 -= factor * Sa2 * Sb1; S22 -= factor * Sa2 * Sb2;

    float cA0 = Sa0 * inv, cA1 = Sa1 * inv, cA2 = Sa2 * inv;
    float cB0 = Sb0 * inv, cB1 = Sb1 * inv, cB2 = Sb2 * inv;

    // Normalize H by Frobenius norm.
    float f2 = S00*S00 + S01*S01 + S02*S02
             + S10*S10 + S11*S11 + S12*S12
             + S20*S20 + S21*S21 + S22*S22;
    float sc = rsqrtf(f2 + 1e-30f);
    float h00 = S00*sc, h01 = S01*sc, h02 = S02*sc;
    float h10 = S10*sc, h11 = S11*sc, h12 = S12*sc;
    float h20 = S20*sc, h21 = S21*sc, h22 = S22*sc;

    // Cofactors, det, ||cof||^2 of normalized H.
    float c00 =  (h11*h22 - h12*h21);
    float c01 = -(h10*h22 - h12*h20);
    float c02 =  (h10*h21 - h11*h20);
    float c10 = -(h01*h22 - h02*h21);
    float c11 =  (h00*h22 - h02*h20);
    float c12 = -(h00*h21 - h01*h20);
    float c20 =  (h01*h12 - h02*h11);
    float c21 = -(h00*h12 - h02*h10);
    float c22 =  (h00*h11 - h01*h10);
    float detH = h00*c00 + h01*c01 + h02*c02;
    float cof2 = c00*c00 + c01*c01 + c02*c02
               + c10*c10 + c11*c11 + c12*c12
               + c20*c20 + c21*c21 + c22*c22;
    float fn = (f2 + 1e-30f) * sc * sc;

    // Char poly of Horn's N: l^4 + C2 l^2 + C1 l + C0; Newton from sqrt(3).
    float C2 = -2.0f * fn;
    float C1 = -8.0f * detH;
    float C0 = fn * fn - 4.0f * cof2;
    float lam = 1.7320508f;
    #pragma unroll
    for (int it = 0; it < 12; it++) {
        float l2 = lam * lam;
        float fv = ((l2 + C2) * lam + C1) * lam + C0;
        float fp = (4.0f * l2 + 2.0f * C2) * lam + C1;
        lam -= __fdividef(fv, fp);
    }

    // M = N - lam*I (Horn's 4x4 symmetric).
    float m00 = (h00 + h11 + h22) - lam;
    float m01 = h12 - h21;
    float m02 = h20 - h02;
    float m03 = h01 - h10;
    float m11 = (h00 - h11 - h22) - lam;
    float m12 = h01 + h10;
    float m13 = h20 + h02;
    float m22 = (h11 - h00 - h22) - lam;
    float m23 = h12 + h21;
    float m33 = (h22 - h00 - h11) - lam;

    #define DET3(a,b,c,d,e,f,g,h,i) ((a)*((e)*(i)-(f)*(h)) - (b)*((d)*(i)-(f)*(g)) + (c)*((d)*(h)-(e)*(g)))
    float A00 =  DET3(m11,m12,m13, m12,m22,m23, m13,m23,m33);
    float A11 =  DET3(m00,m02,m03, m02,m22,m23, m03,m23,m33);
    float A22 =  DET3(m00,m01,m03, m01,m11,m13, m03,m13,m33);
    float A33 =  DET3(m00,m01,m02, m01,m11,m12, m02,m12,m22);
    float A01 = -DET3(m01,m12,m13, m02,m22,m23, m03,m23,m33);
    float A02 =  DET3(m01,m11,m13, m02,m12,m23, m03,m13,m33);
    float A03 = -DET3(m01,m11,m12, m02,m12,m22, m03,m13,m23);
    float A12 = -DET3(m00,m01,m03, m02,m12,m23, m03,m13,m33);
    float A13 =  DET3(m00,m01,m02, m02,m12,m22, m03,m13,m23);
    float A23 = -DET3(m00,m01,m02, m01,m11,m12, m03,m13,m23);
    #undef DET3

    float best = fabsf(A00);
    float q0 = A00, qx = A01, qy = A02, qz = A03;
    float d1 = fabsf(A11);
    if (d1 > best) { best = d1; q0 = A01; qx = A11; qy = A12; qz = A13; }
    float d2 = fabsf(A22);
    if (d2 > best) { best = d2; q0 = A02; qx = A12; qy = A22; qz = A23; }
    float d3 = fabsf(A33);
    if (d3 > best) { best = d3; q0 = A03; qx = A13; qy = A23; qz = A33; }

    float qn = rsqrtf(q0*q0 + qx*qx + qy*qy + qz*qz + 1e-30f);
    q0 *= qn; qx *= qn; qy *= qn; qz *= qn;

    float xx = qx*qx, yy = qy*qy, zz = qz*qz;
    float xy = qx*qy, xz = qx*qz, yz = qy*qz;
    float wx = q0*qx, wy = q0*qy, wz = q0*qz;
    float r00 = 1.0f - 2.0f*(yy + zz);
    float r01 = 2.0f*(xy - wz);
    float r02 = 2.0f*(xz + wy);
    float r10 = 2.0f*(xy + wz);
    float r11 = 1.0f - 2.0f*(xx + zz);
    float r12 = 2.0f*(yz - wx);
    float r20 = 2.0f*(xz - wy);
    float r21 = 2.0f*(yz + wx);
    float r22 = 1.0f - 2.0f*(xx + yy);

    float t0 = cB0 - (r00*cA0 + r01*cA1 + r02*cA2);
    float t1 = cB1 - (r10*cA0 + r11*cA1 + r12*cA2);
    float t2 = cB2 - (r20*cA0 + r21*cA1 + r22*cA2);

    float4* o = reinterpret_cast<float4*>(out) + b * 4;
    o[0] = make_float4(r00, r01, r02, t0);
    o[1] = make_float4(r10, r11, r12, t1);
    o[2] = make_float4(r20, r21, r22, t2);
    o[3] = make_float4(0.0f, 0.0f, 0.0f, 1.0f);
}

extern "C" void kernel_launch(void* const* d_in, const int* in_sizes, int n_in,
                              void* d_out, int out_size)
{
    const float4* A = (const float4*)d_in[0];
    const float4* B = (const float4*)d_in[1];
    const float4* W = (const float4*)d_in[2];
    int bs = in_sizes[2] / 20;   // weights: [bs, 20]
    int blocks = (bs + BPC - 1) / BPC;
    kabsch_kernel<<<blocks, WARPS * 32>>>(A, B, W, (float*)d_out, bs);
}